// round 2
// baseline (speedup 1.0000x reference)
#include <cuda_runtime.h>

// RelationCrossing: feats (R=8, N, K=8, d=64) fp32, rel_attn (8, 64) fp32.
// scores[r,n,k] = leaky_relu(dot(feats[r,n,k,:], rel_attn[k,:]), 0.2)
// attn = softmax over r; out[n,k,:] = sum_r attn[r,n,k] * feats[r,n,k,:]
//
// Single-pass, SMEM-resident via cp.async: each thread handles a float4
// (4 d-values) of one (n,k). The 8 relation values per thread are staged in
// shared memory by LDGSTS (global->smem, register-free), cutting regs/thread
// from 54 to ~32 so occupancy rises from 44% to ~80% and DRAM stays saturated
// across load-batch tails and wave transitions.
// 16 consecutive threads cover one head; dot product reduced with xor-shuffles.
// feats read exactly once (1.638 GB), out written once (0.205 GB).

#define R 8
#define NEG_SLOPE 0.2f

__device__ __forceinline__ void cp_async16(void* smem_ptr, const void* gmem_ptr) {
    unsigned saddr = (unsigned)__cvta_generic_to_shared(smem_ptr);
    asm volatile("cp.async.cg.shared.global [%0], [%1], 16;\n"
                 :: "r"(saddr), "l"(gmem_ptr) : "memory");
}

__global__ __launch_bounds__(256, 6) void relation_crossing_kernel(
    const float4* __restrict__ feats,   // R * N * 128 float4s
    const float4* __restrict__ rel,     // 128 float4s (8 heads * 16 quarters)
    float4* __restrict__ out,           // N * 128 float4s
    int total4,                         // N * 128
    long long rel_stride4)              // N * 128 (float4 stride between relations)
{
    // [r][tid] layout: lane addresses consecutive 16B -> conflict-free LDS.128
    __shared__ float4 buf[R][256];

    int tid = threadIdx.x;
    int idx = blockIdx.x * blockDim.x + tid;
    if (idx >= total4) return;   // no barriers below; early-exit is safe

    // Stage all 8 relation float4s into SMEM, register-free, 8-deep MLP.
#pragma unroll
    for (int r = 0; r < R; r++)
        cp_async16(&buf[r][tid], &feats[(long long)r * rel_stride4 + idx]);
    asm volatile("cp.async.commit_group;\n" ::: "memory");

    // idx = n*128 + k*16 + q  (k = head, q = d-quarter); rel index = k*16+q.
    float4 ra = __ldg(&rel[idx & 127]);

    asm volatile("cp.async.wait_group 0;\n" ::: "memory");

    // Partial dot products from SMEM.
    float s[R];
#pragma unroll
    for (int r = 0; r < R; r++) {
        float4 f = buf[r][tid];
        s[r] = f.x * ra.x + f.y * ra.y + f.z * ra.z + f.w * ra.w;
    }

    // Reduce across the 16-thread group covering this head (warp-aligned).
#pragma unroll
    for (int off = 8; off >= 1; off >>= 1) {
#pragma unroll
        for (int r = 0; r < R; r++)
            s[r] += __shfl_xor_sync(0xffffffffu, s[r], off);
    }

    // leaky_relu + softmax over relations (identical in all 16 group threads).
    float m = -3.4e38f;
#pragma unroll
    for (int r = 0; r < R; r++) {
        s[r] = (s[r] > 0.0f) ? s[r] : NEG_SLOPE * s[r];
        m = fmaxf(m, s[r]);
    }
    float sum = 0.0f;
#pragma unroll
    for (int r = 0; r < R; r++) {
        s[r] = __expf(s[r] - m);
        sum += s[r];
    }
    float inv = __frcp_rn(sum);

    // Weighted sum, second SMEM pass (still conflict-free).
    float4 o = make_float4(0.f, 0.f, 0.f, 0.f);
#pragma unroll
    for (int r = 0; r < R; r++) {
        float w = s[r] * inv;
        float4 f = buf[r][tid];
        o.x = fmaf(w, f.x, o.x);
        o.y = fmaf(w, f.y, o.y);
        o.z = fmaf(w, f.z, o.z);
        o.w = fmaf(w, f.w, o.w);
    }
    out[idx] = o;
}

extern "C" void kernel_launch(void* const* d_in, const int* in_sizes, int n_in,
                              void* d_out, int out_size)
{
    const float4* feats = (const float4*)d_in[0];  // (8, N, 512) fp32
    const float4* rel   = (const float4*)d_in[1];  // (8, 64) fp32
    float4* out = (float4*)d_out;                  // (N, 512) fp32

    long long elems_per_rel = (long long)in_sizes[0] / R;   // N*512 floats
    int total4 = (int)(elems_per_rel / 4);                  // N*128 float4
    long long rel_stride4 = total4;

    int threads = 256;
    int blocks = (total4 + threads - 1) / threads;
    relation_crossing_kernel<<<blocks, threads>>>(feats, rel, out, total4, rel_stride4);
}

// round 3
// speedup vs baseline: 1.0874x; 1.0874x over previous
#include <cuda_runtime.h>

// RelationCrossing: feats (R=8, N, K=8, d=64) fp32, rel_attn (8, 64) fp32.
// scores[r,n,k] = leaky_relu(dot(feats[r,n,k,:], rel_attn[k,:]), 0.2)
// attn = softmax over r; out[n,k,:] = sum_r attn[r,n,k] * feats[r,n,k,:]
//
// Single-pass, register-resident (R1 scheme), float2 granularity:
// each thread owns 2 d-values of one (n,k); a FULL WARP (32 threads) covers
// one head (64 floats). f[8] costs 16 regs instead of 32 -> ~40 regs/thread
// -> 6 CTAs/SM (vs 4), giving more phase diversity so DRAM demand stays
// continuous through each warp's shuffle/softmax tail.
// feats read exactly once (1.638 GB), out written once (0.205 GB) — traffic floor.

#define R 8
#define NEG_SLOPE 0.2f

__global__ __launch_bounds__(256, 6) void relation_crossing_kernel(
    const float2* __restrict__ feats,   // R * N * 256 float2s
    const float2* __restrict__ rel,     // 256 float2s (8 heads * 32 halves)
    float2* __restrict__ out,           // N * 256 float2s
    int total2,                         // N * 256
    long long rel_stride2)              // N * 256 (float2 stride between relations)
{
    int idx = blockIdx.x * blockDim.x + threadIdx.x;
    if (idx >= total2) return;

    // idx = n*256 + k*32 + h  (k = head, h = d-half-pair). rel index = k*32+h.
    float2 ra = __ldg(&rel[idx & 255]);

    // Front-batched loads: 8 independent LDG.64, scoreboard-interleaved.
    float2 f[R];
    float s[R];
#pragma unroll
    for (int r = 0; r < R; r++) {
        f[r] = feats[(long long)r * rel_stride2 + idx];
        s[r] = f[r].x * ra.x + f[r].y * ra.y;
    }

    // Full-warp butterfly reduce: every lane ends with all 8 head-dot-products.
#pragma unroll
    for (int off = 16; off >= 1; off >>= 1) {
#pragma unroll
        for (int r = 0; r < R; r++)
            s[r] += __shfl_xor_sync(0xffffffffu, s[r], off);
    }

    // leaky_relu + softmax over relations (identical across the warp's head).
    float m = -3.4e38f;
#pragma unroll
    for (int r = 0; r < R; r++) {
        s[r] = (s[r] > 0.0f) ? s[r] : NEG_SLOPE * s[r];
        m = fmaxf(m, s[r]);
    }
    float sum = 0.0f;
#pragma unroll
    for (int r = 0; r < R; r++) {
        s[r] = __expf(s[r] - m);
        sum += s[r];
    }
    float inv = __frcp_rn(sum);

    float2 o = make_float2(0.f, 0.f);
#pragma unroll
    for (int r = 0; r < R; r++) {
        float w = s[r] * inv;
        o.x = fmaf(w, f[r].x, o.x);
        o.y = fmaf(w, f[r].y, o.y);
    }
    out[idx] = o;
}

extern "C" void kernel_launch(void* const* d_in, const int* in_sizes, int n_in,
                              void* d_out, int out_size)
{
    const float2* feats = (const float2*)d_in[0];  // (8, N, 512) fp32
    const float2* rel   = (const float2*)d_in[1];  // (8, 64) fp32
    float2* out = (float2*)d_out;                  // (N, 512) fp32

    long long elems_per_rel = (long long)in_sizes[0] / R;   // N*512 floats
    int total2 = (int)(elems_per_rel / 2);                  // N*256 float2
    long long rel_stride2 = total2;

    int threads = 256;
    int blocks = (total2 + threads - 1) / threads;
    relation_crossing_kernel<<<blocks, threads>>>(feats, rel, out, total2, rel_stride2);
}

// round 5
// speedup vs baseline: 1.1749x; 1.0805x over previous
#include <cuda_runtime.h>

// RelationCrossing: feats (R=8, N, K=8, d=64) fp32, rel_attn (8, 64) fp32.
// scores[r,n,k] = leaky_relu(dot(feats[r,n,k,:], rel_attn[k,:]), 0.2)
// attn = softmax over r; out[n,k,:] = sum_r attn[r,n,k] * feats[r,n,k,:]
//
// R1 register-resident float4 scheme (best: 254us, DRAM 91.8%) with:
//  - 128-thread blocks, 9 CTAs/SM (36 warps vs 32; 3x finer CTA granularity
//    so per-warp load/compute-tail phases desynchronize across the SM).
//  - __ldcs / __stcs streaming hints: every byte touched exactly once,
//    evict-first keeps L2 allocation pressure off the 8:1 read:write stream.
// (redux.sync.add.f32 is NOT available on sm_103 — butterfly retained.)
// feats read once (1.638 GB), out written once (0.205 GB) — traffic floor.

#define R 8
#define NEG_SLOPE 0.2f

__global__ __launch_bounds__(128, 9) void relation_crossing_kernel(
    const float4* __restrict__ feats,   // R * N * 128 float4s
    const float4* __restrict__ rel,     // 128 float4s (8 heads * 16 quarters)
    float4* __restrict__ out,           // N * 128 float4s
    int total4,                         // N * 128
    long long rel_stride4)              // N * 128 (float4 stride between relations)
{
    int idx = blockIdx.x * blockDim.x + threadIdx.x;
    if (idx >= total4) return;

    // idx = n*128 + k*16 + q  (k = head, q = d-quarter). rel index = k*16+q.
    float4 ra = __ldg(&rel[idx & 127]);

    // Front-batched loads: 8 independent LDG.128.CS (streamed, evict-first).
    float4 f[R];
    float s[R];
#pragma unroll
    for (int r = 0; r < R; r++) {
        f[r] = __ldcs(&feats[(long long)r * rel_stride4 + idx]);
        s[r] = f[r].x * ra.x + f[r].y * ra.y + f[r].z * ra.z + f[r].w * ra.w;
    }

    // Reduce dot products across the 16-thread group covering this head.
    // Groups of 16 are warp-aligned; 4 butterfly levels, 8 independent values
    // per level so the serial chain is 4 SHFL latencies.
#pragma unroll
    for (int off = 8; off >= 1; off >>= 1) {
#pragma unroll
        for (int r = 0; r < R; r++)
            s[r] += __shfl_xor_sync(0xffffffffu, s[r], off);
    }

    // leaky_relu + softmax over relations (identical across the 16-lane group).
    float m = -3.4e38f;
#pragma unroll
    for (int r = 0; r < R; r++) {
        s[r] = (s[r] > 0.0f) ? s[r] : NEG_SLOPE * s[r];
        m = fmaxf(m, s[r]);
    }
    float sum = 0.0f;
#pragma unroll
    for (int r = 0; r < R; r++) {
        s[r] = __expf(s[r] - m);
        sum += s[r];
    }
    float inv = __frcp_rn(sum);

    float4 o = make_float4(0.f, 0.f, 0.f, 0.f);
#pragma unroll
    for (int r = 0; r < R; r++) {
        float w = s[r] * inv;
        o.x = fmaf(w, f[r].x, o.x);
        o.y = fmaf(w, f[r].y, o.y);
        o.z = fmaf(w, f[r].z, o.z);
        o.w = fmaf(w, f[r].w, o.w);
    }
    __stcs(&out[idx], o);
}

extern "C" void kernel_launch(void* const* d_in, const int* in_sizes, int n_in,
                              void* d_out, int out_size)
{
    const float4* feats = (const float4*)d_in[0];  // (8, N, 512) fp32
    const float4* rel   = (const float4*)d_in[1];  // (8, 64) fp32
    float4* out = (float4*)d_out;                  // (N, 512) fp32

    long long elems_per_rel = (long long)in_sizes[0] / R;   // N*512 floats
    int total4 = (int)(elems_per_rel / 4);                  // N*128 float4
    long long rel_stride4 = total4;

    int threads = 128;
    int blocks = (total4 + threads - 1) / threads;
    relation_crossing_kernel<<<blocks, threads>>>(feats, rel, out, total4, rel_stride4);
}